// round 1
// baseline (speedup 1.0000x reference)
#include <cuda_runtime.h>
#include <cuda_bf16.h>
#include <cstdint>

#define B_   32
#define S_   4096
#define T_   8192
#define DIN  128
#define DT   256
#define M_   (B_ * T_)   // 262144

// ---------------- scratch (device globals: no runtime allocation) ----------
__device__ float g_pos_emb[T_ * DIN];                 // 4 MB
__device__ float g_comb[(size_t)M_ * DT];             // 256 MB
__device__ float g_slens[B_];
__device__ float g_w[4];

__device__ __forceinline__ float gelu_exact(float x) {
    return 0.5f * x * (1.0f + erff(x * 0.70710678118654752440f));
}

// ---------------- kernel 1: s_lens + neighbor softmax ----------------------
__global__ void k_prep(const float* __restrict__ s_mask,
                       const float* __restrict__ nw) {
    int tid  = threadIdx.x;           // 1024 threads = 32 warps
    int w    = tid >> 5;
    int lane = tid & 31;
    const float* row = s_mask + (size_t)w * S_;
    float s = 0.f;
    for (int i = lane; i < S_; i += 32) s += row[i];
    #pragma unroll
    for (int o = 16; o; o >>= 1) s += __shfl_xor_sync(0xFFFFFFFFu, s, o);
    if (lane == 0) g_slens[w] = s;
    if (tid == 0) {
        float a = nw[0], b = nw[1], c = nw[2];
        float m = fmaxf(a, fmaxf(b, c));
        float ea = expf(a - m), eb = expf(b - m), ec = expf(c - m);
        float inv = 1.f / (ea + eb + ec);
        g_w[0] = ea * inv; g_w[1] = eb * inv; g_w[2] = ec * inv;
    }
}

// ---------------- kernel 2: pos_emb[T,128] table ---------------------------
__global__ void k_posemb(const float* __restrict__ w1, const float* __restrict__ b1,
                         const float* __restrict__ w2, const float* __restrict__ b2) {
    __shared__ float h[64];
    int t   = blockIdx.x;
    int tid = threadIdx.x;            // 128 threads
    const float step = 1.0f / (float)(T_ - 1);
    float pos = (float)t * step;
    if (tid < 64) {
        float x = pos * w1[tid] + b1[tid];
        h[tid] = gelu_exact(x);
    }
    __syncthreads();
    float acc = b2[tid];
    #pragma unroll 16
    for (int j = 0; j < 64; j++)
        acc = fmaf(h[j], w2[j * DIN + tid], acc);
    g_pos_emb[(size_t)t * DIN + tid] = acc;
}

// ---------------- kernel 3: gather/blend -> combined[M,256] ----------------
__global__ void k_combined(const float* __restrict__ emb,
                           const float* __restrict__ s_mask) {
    int warp = threadIdx.x >> 5;      // 8 warps / block, 1 row each
    int lane = threadIdx.x & 31;
    int m = blockIdx.x * 8 + warp;
    int b = m >> 13;                  // T_ = 2^13
    int t = m & (T_ - 1);

    float slen = g_slens[b];
    const float step = 1.0f / (float)(T_ - 1);
    float pos = (float)t * step;      // matches jnp.linspace op order
    float sp  = pos * (slen - 1.0f);  // matches pos_grid * (s_lens - 1.0)
    int curr  = (int)sp;              // trunc == floor (nonneg)
    int prev  = max(curr - 1, 0);
    int nxt   = min(curr + 1, S_ - 1);

    const float* mrow = s_mask + (size_t)b * S_;
    float w0 = g_w[0] * mrow[prev];
    float w1 = g_w[1] * mrow[curr];
    float w2 = g_w[2] * mrow[nxt];

    const float4* ep = (const float4*)(emb + ((size_t)b * S_ + prev) * DIN);
    const float4* ec = (const float4*)(emb + ((size_t)b * S_ + curr) * DIN);
    const float4* en = (const float4*)(emb + ((size_t)b * S_ + nxt)  * DIN);
    float4 vp = ep[lane], vc = ec[lane], vn = en[lane];
    float4 o;
    o.x = w0 * vp.x + w1 * vc.x + w2 * vn.x;
    o.y = w0 * vp.y + w1 * vc.y + w2 * vn.y;
    o.z = w0 * vp.z + w1 * vc.z + w2 * vn.z;
    o.w = w0 * vp.w + w1 * vc.w + w2 * vn.w;

    float4* dst = (float4*)(g_comb + (size_t)m * DT);
    dst[lane] = o;
    const float4* pe = (const float4*)(g_pos_emb + (size_t)t * DIN);
    dst[32 + lane] = pe[lane];
}

// ---------------- kernel 4: GEMM + gelu + layernorm + mask -----------------
// Block: 64 rows x 256 cols, 256 threads (8 warps).
// Thread (tx,ty): rows ty*8+i (i<8), col-pairs {64*j+2*tx, +1} (j<4).
// Warp ty owns 8 full rows -> per-row layernorm is a warp shuffle reduce.
// Accumulate with packed fma.rn.f32x2 (2x FFMA throughput on sm_103a).
__global__ void __launch_bounds__(256, 2)
k_gemm(const float* __restrict__ W, const float* __restrict__ bias,
       const float* __restrict__ lng, const float* __restrict__ lnb,
       const float* __restrict__ tmask, float* __restrict__ out) {
    __shared__ float As[64][33];
    __shared__ __align__(16) float Bs[32][DT];

    int tid = threadIdx.x;
    int tx  = tid & 31;
    int ty  = tid >> 5;
    int m0  = blockIdx.x * 64;

    unsigned long long acc[8][4];
    #pragma unroll
    for (int i = 0; i < 8; i++)
        #pragma unroll
        for (int j = 0; j < 4; j++) acc[i][j] = 0ull;  // (0.f, 0.f)

    const float* combBase = g_comb + (size_t)m0 * DT;

    for (int k0 = 0; k0 < DT; k0 += 32) {
        // A tile: warp ty loads its 8 rows, col k0+tx (coalesced)
        #pragma unroll
        for (int i = 0; i < 8; i++) {
            int mr = ty * 8 + i;
            As[mr][tx] = combBase[(size_t)mr * DT + k0 + tx];
        }
        // B tile: 32x256 floats as float4 (coalesced)
        #pragma unroll
        for (int i = 0; i < 8; i++) {
            int idx = i * 256 + tid;          // float4 index
            int kk  = idx >> 6;
            int c4  = idx & 63;
            ((float4*)&Bs[kk][0])[c4] =
                ((const float4*)(W + (size_t)(k0 + kk) * DT))[c4];
        }
        __syncthreads();

        #pragma unroll 16
        for (int k = 0; k < 32; k++) {
            unsigned long long b2[4];
            #pragma unroll
            for (int j = 0; j < 4; j++)       // LDS.64, lanes contiguous: conflict-free
                b2[j] = *(const unsigned long long*)&Bs[k][j * 64 + tx * 2];
            #pragma unroll
            for (int i = 0; i < 8; i++) {
                unsigned int au = __float_as_uint(As[ty * 8 + i][k]); // broadcast LDS
                unsigned long long a2;
                asm("mov.b64 %0, {%1, %1};" : "=l"(a2) : "r"(au));
                #pragma unroll
                for (int j = 0; j < 4; j++)
                    asm("fma.rn.f32x2 %0, %1, %2, %0;"
                        : "+l"(acc[i][j]) : "l"(a2), "l"(b2[j]));
            }
        }
        __syncthreads();
    }

    // epilogue params for this thread's columns
    float2 bia[4], gg[4], bb[4];
    #pragma unroll
    for (int j = 0; j < 4; j++) {
        int c = j * 64 + tx * 2;
        bia[j] = *(const float2*)&bias[c];
        gg[j]  = *(const float2*)&lng[c];
        bb[j]  = *(const float2*)&lnb[c];
    }

    #pragma unroll
    for (int i = 0; i < 8; i++) {
        int m = m0 + ty * 8 + i;
        float v[8];
        float s = 0.f, s2 = 0.f;
        #pragma unroll
        for (int j = 0; j < 4; j++) {
            float lo = __uint_as_float((unsigned int)(acc[i][j] & 0xFFFFFFFFull));
            float hi = __uint_as_float((unsigned int)(acc[i][j] >> 32));
            lo = gelu_exact(lo + bia[j].x);
            hi = gelu_exact(hi + bia[j].y);
            v[2 * j] = lo; v[2 * j + 1] = hi;
            s  += lo + hi;
            s2 += lo * lo + hi * hi;
        }
        #pragma unroll
        for (int o = 16; o; o >>= 1) {
            s  += __shfl_xor_sync(0xFFFFFFFFu, s,  o);
            s2 += __shfl_xor_sync(0xFFFFFFFFu, s2, o);
        }
        float mu  = s * (1.0f / 256.0f);
        float var = s2 * (1.0f / 256.0f) - mu * mu;
        float inv = rsqrtf(var + 1e-5f);
        float mk  = tmask[m];                 // tmask is [B,T], m = b*T+t
        #pragma unroll
        for (int j = 0; j < 4; j++) {
            float2 r;
            r.x = ((v[2 * j]     - mu) * inv * gg[j].x + bb[j].x) * mk;
            r.y = ((v[2 * j + 1] - mu) * inv * gg[j].y + bb[j].y) * mk;
            *(float2*)&out[(size_t)m * DT + j * 64 + tx * 2] = r;
        }
    }
}

// ---------------- launch ---------------------------------------------------
extern "C" void kernel_launch(void* const* d_in, const int* in_sizes, int n_in,
                              void* d_out, int out_size) {
    const float* student_emb = (const float*)d_in[0];
    const float* s_mask      = (const float*)d_in[1];
    const float* t_mask      = (const float*)d_in[2];
    // target_length may or may not be materialized as an input; pe_w1 has 64 elems.
    int p = (in_sizes[3] == 64) ? 3 : 4;
    const float* pe_w1 = (const float*)d_in[p + 0];
    const float* pe_b1 = (const float*)d_in[p + 1];
    const float* pe_w2 = (const float*)d_in[p + 2];
    const float* pe_b2 = (const float*)d_in[p + 3];
    const float* pt_w  = (const float*)d_in[p + 4];
    const float* pt_b  = (const float*)d_in[p + 5];
    const float* ln_g  = (const float*)d_in[p + 6];
    const float* ln_b  = (const float*)d_in[p + 7];
    const float* nw    = (const float*)d_in[p + 8];
    float* out = (float*)d_out;

    k_prep<<<1, 1024>>>(s_mask, nw);
    k_posemb<<<T_, 128>>>(pe_w1, pe_b1, pe_w2, pe_b2);
    k_combined<<<M_ / 8, 256>>>(student_emb, s_mask);
    k_gemm<<<M_ / 64, 256>>>(pt_w, pt_b, ln_g, ln_b, t_mask, out);
}

// round 3
// speedup vs baseline: 1.6935x; 1.6935x over previous
#include <cuda_runtime.h>
#include <cuda_bf16.h>
#include <cstdint>

#define B_   32
#define S_   4096
#define T_   8192
#define DIN  128
#define DT   256
#define M_   (B_ * T_)        // 262144
#define TILE_M 64
#define NBLK  (M_ / TILE_M)   // 4096

// ---------------- device-global tables (no runtime allocation) -------------
__device__ float    g_slens[B_];
__device__ float    g_w[4];
__device__ uint16_t g_whi[DT * DT];     // W bf16 hi, [k][n] row-major
__device__ uint16_t g_wlo[DT * DT];     // W bf16 lo
__device__ uint32_t g_pehi[T_ * 64];    // pos_emb packed bf16x2 hi, [t][pair]
__device__ uint32_t g_pelo[T_ * 64];

// ---------------- smem layout ----------------------------------------------
#define OFF_BIAS 0
#define OFF_G    1024
#define OFF_BETA 2048
#define OFF_PS   3072          // float[256]: psum[row][wn]
#define OFF_PS2  4096
#define OFF_A_HI 5120
#define A_PITCH  528           // 264 bf16 per row (pad for conflict-free ldmatrix)
#define OFF_A_LO (OFF_A_HI + 64 * A_PITCH)      // 38912
#define OFF_B0   (OFF_A_LO + 64 * A_PITCH)      // 72704
#define B_PITCH  528
#define B_MAT    (32 * B_PITCH)                 // 16896 (one matrix, one chunk)
#define B_STAGE  (2 * B_MAT)                    // hi + lo
#define SMEM_TOTAL (OFF_B0 + 2 * B_STAGE)       // 140288

// ---------------- asm helpers ----------------------------------------------
__device__ __forceinline__ uint32_t smem_u32(const void* p) {
    uint32_t a;
    asm("{ .reg .u64 t; cvta.to.shared.u64 t, %1; cvt.u32.u64 %0, t; }" : "=r"(a) : "l"(p));
    return a;
}
#define CP_ASYNC16(dst, src) \
    asm volatile("cp.async.cg.shared.global [%0], [%1], 16;" :: "r"(dst), "l"(src))
#define CP_COMMIT() asm volatile("cp.async.commit_group;" ::: "memory")
#define CP_WAIT0()  asm volatile("cp.async.wait_group 0;" ::: "memory")

#define LDSM4(r, addr) \
    asm volatile("ldmatrix.sync.aligned.m8n8.x4.shared.b16 {%0,%1,%2,%3}, [%4];" \
        : "=r"((r)[0]), "=r"((r)[1]), "=r"((r)[2]), "=r"((r)[3]) : "r"(addr))
#define LDSM4T(r, addr) \
    asm volatile("ldmatrix.sync.aligned.m8n8.x4.trans.shared.b16 {%0,%1,%2,%3}, [%4];" \
        : "=r"((r)[0]), "=r"((r)[1]), "=r"((r)[2]), "=r"((r)[3]) : "r"(addr))

__device__ __forceinline__ void mma_bf16(float* c, const uint32_t* a, const uint32_t* b) {
    asm volatile("mma.sync.aligned.m16n8k16.row.col.f32.bf16.bf16.f32 "
        "{%0,%1,%2,%3}, {%4,%5,%6,%7}, {%8,%9}, {%0,%1,%2,%3};"
        : "+f"(c[0]), "+f"(c[1]), "+f"(c[2]), "+f"(c[3])
        : "r"(a[0]), "r"(a[1]), "r"(a[2]), "r"(a[3]), "r"(b[0]), "r"(b[1]));
}

// packs (x0 -> low half, x1 -> high half)
#define CVT2(result, x0, x1) \
    asm("cvt.rn.satfinite.bf16x2.f32 %0, %1, %2;" : "=r"(result) : "f"(x1), "f"(x0))

__device__ __forceinline__ float gelu_exact(float x) {
    return 0.5f * x * (1.0f + erff(x * 0.70710678118654752440f));
}

// ---------------- kernel 1: s_lens + neighbor softmax ----------------------
__global__ void k_prep(const float* __restrict__ s_mask, const float* __restrict__ nw) {
    int tid = threadIdx.x, w = tid >> 5, lane = tid & 31;
    const float* row = s_mask + (size_t)w * S_;
    float s = 0.f;
    for (int i = lane; i < S_; i += 32) s += row[i];
    #pragma unroll
    for (int o = 16; o; o >>= 1) s += __shfl_xor_sync(0xFFFFFFFFu, s, o);
    if (lane == 0) g_slens[w] = s;
    if (tid == 0) {
        float a = nw[0], b = nw[1], c = nw[2];
        float m = fmaxf(a, fmaxf(b, c));
        float ea = expf(a - m), eb = expf(b - m), ec = expf(c - m);
        float inv = 1.f / (ea + eb + ec);
        g_w[0] = ea * inv; g_w[1] = eb * inv; g_w[2] = ec * inv;
    }
}

// ---------------- kernel 2: pos_emb -> packed bf16x2 hi/lo [t][64] ---------
__global__ void k_posemb(const float* __restrict__ w1, const float* __restrict__ b1,
                         const float* __restrict__ w2, const float* __restrict__ b2) {
    __shared__ float h[64];
    int t = blockIdx.x, tid = threadIdx.x;   // 128 threads
    float pos = (float)t * (1.0f / (float)(T_ - 1));
    if (tid < 64) h[tid] = gelu_exact(pos * w1[tid] + b1[tid]);
    __syncthreads();
    float acc = b2[tid];
    #pragma unroll 16
    for (int j = 0; j < 64; j++) acc = fmaf(h[j], w2[j * DIN + tid], acc);
    float x1 = __shfl_down_sync(0xFFFFFFFFu, acc, 1);
    if ((tid & 1) == 0) {
        uint32_t ph; CVT2(ph, acc, x1);
        float l0 = acc - __uint_as_float(ph << 16);
        float l1 = x1  - __uint_as_float(ph & 0xFFFF0000u);
        uint32_t pl; CVT2(pl, l0, l1);
        g_pehi[t * 64 + (tid >> 1)] = ph;
        g_pelo[t * 64 + (tid >> 1)] = pl;
    }
}

// ---------------- kernel 3: W -> bf16 hi/lo [k][n] -------------------------
__global__ void k_wsplit(const float* __restrict__ W) {
    int idx = blockIdx.x * 256 + threadIdx.x;   // 65536
    float x = W[idx];
    __nv_bfloat16 hb = __float2bfloat16(x);
    float hf = __bfloat162float(hb);
    __nv_bfloat16 lb = __float2bfloat16(x - hf);
    __nv_bfloat16_raw hr = hb, lr = lb;
    g_whi[idx] = hr.x;
    g_wlo[idx] = lr.x;
}

// ---------------- B chunk loader (cp.async, 8 x 16B per thread) ------------
__device__ __forceinline__ void load_B_chunk(uint32_t sb, int stage, int chunk, int tid) {
    uint32_t dst = sb + OFF_B0 + stage * B_STAGE;
    const char* shi = (const char*)(g_whi + chunk * 32 * DT);
    const char* slo = (const char*)(g_wlo + chunk * 32 * DT);
    #pragma unroll
    for (int i = 0; i < 8; i++) {
        int f   = tid + 256 * i;           // 0..2047
        int mat = f >> 10;                 // 0=hi, 1=lo
        int r   = (f >> 5) & 31;
        int c   = f & 31;                  // 16B segment
        const char* src = (mat ? slo : shi) + (size_t)r * 512 + c * 16;
        CP_ASYNC16(dst + mat * B_MAT + r * B_PITCH + c * 16, src);
    }
}

// ---------------- kernel 4: fused gather + bf16-split GEMM + epilogue ------
__global__ void __launch_bounds__(256, 1)
k_main(const float* __restrict__ emb, const float* __restrict__ s_mask,
       const float* __restrict__ tmask,
       const float* __restrict__ bias, const float* __restrict__ lng,
       const float* __restrict__ lnb, float* __restrict__ out) {
    extern __shared__ char smem[];
    uint32_t sb = smem_u32(smem);
    int tid = threadIdx.x, wid = tid >> 5, lane = tid & 31;
    int wm = wid >> 2;        // 0..1 : M half (32 rows)
    int wn = wid & 3;         // 0..3 : N quarter (64 cols)
    int m0 = blockIdx.x * TILE_M;
    int t0 = m0 & (T_ - 1);   // all 64 rows share batch b (T divisible by 64)
    int b  = m0 >> 13;

    // epilogue params to smem
    ((float*)(smem + OFF_BIAS))[tid] = bias[tid];
    ((float*)(smem + OFF_G))[tid]    = lng[tid];
    ((float*)(smem + OFF_BETA))[tid] = lnb[tid];

    // prefetch B chunk 0
    load_B_chunk(sb, 0, 0, tid);
    CP_COMMIT();

    // ---- produce A tile (64 x 256) in smem as bf16 hi/lo ----
    {
        float slen = g_slens[b];
        float wv0 = g_w[0], wv1 = g_w[1], wv2 = g_w[2];
        const float* mrow = s_mask + (size_t)b * S_;
        #pragma unroll 2
        for (int i = 0; i < 8; i++) {
            int row = wid * 8 + i;
            int t = t0 + row;
            float pos = (float)t * (1.0f / (float)(T_ - 1));
            float sp  = pos * (slen - 1.0f);
            int curr = (int)sp;
            int prev = max(curr - 1, 0);
            int nxt  = min(curr + 1, S_ - 1);
            float w0 = wv0 * mrow[prev];
            float w1 = wv1 * mrow[curr];
            float w2 = wv2 * mrow[nxt];
            const float4* ep = (const float4*)(emb + ((size_t)b * S_ + prev) * DIN);
            const float4* ec = (const float4*)(emb + ((size_t)b * S_ + curr) * DIN);
            const float4* en = (const float4*)(emb + ((size_t)b * S_ + nxt)  * DIN);
            float4 vp = ep[lane], vc = ec[lane], vn = en[lane];
            float v0 = w0 * vp.x + w1 * vc.x + w2 * vn.x;
            float v1 = w0 * vp.y + w1 * vc.y + w2 * vn.y;
            float v2 = w0 * vp.z + w1 * vc.z + w2 * vn.z;
            float v3 = w0 * vp.w + w1 * vc.w + w2 * vn.w;
            uint32_t h0; CVT2(h0, v0, v1);
            uint32_t h1; CVT2(h1, v2, v3);
            float l00 = v0 - __uint_as_float(h0 << 16);
            float l01 = v1 - __uint_as_float(h0 & 0xFFFF0000u);
            float l10 = v2 - __uint_as_float(h1 << 16);
            float l11 = v3 - __uint_as_float(h1 & 0xFFFF0000u);
            uint32_t q0; CVT2(q0, l00, l01);
            uint32_t q1; CVT2(q1, l10, l11);
            // blended -> cols [4*lane .. 4*lane+3]
            *(uint2*)(smem + OFF_A_HI + row * A_PITCH + 8 * lane) = make_uint2(h0, h1);
            *(uint2*)(smem + OFF_A_LO + row * A_PITCH + 8 * lane) = make_uint2(q0, q1);
            // pos_emb -> cols [128 .. 255]
            uint2 peh = *(const uint2*)(g_pehi + (size_t)t * 64 + 2 * lane);
            uint2 pel = *(const uint2*)(g_pelo + (size_t)t * 64 + 2 * lane);
            *(uint2*)(smem + OFF_A_HI + row * A_PITCH + 256 + 8 * lane) = peh;
            *(uint2*)(smem + OFF_A_LO + row * A_PITCH + 256 + 8 * lane) = pel;
        }
    }
    CP_WAIT0();
    __syncthreads();

    // ---- ldmatrix lane addresses ----
    int xr = (lane & 7) + ((lane >> 3) & 1) * 8;   // 0..15
    int xg = lane >> 4;                            // 0..1
    uint32_t a_hi = sb + OFF_A_HI + (wm * 32 + xr) * A_PITCH + xg * 16;
    uint32_t a_lo = a_hi + (OFF_A_LO - OFF_A_HI);
    uint32_t b_off = xr * B_PITCH + (wn * 64 + xg * 8) * 2;   // + stage/mat/k0*B_PITCH + nt*32

    float acc[2][8][4];
    #pragma unroll
    for (int mt = 0; mt < 2; mt++)
        #pragma unroll
        for (int nt = 0; nt < 8; nt++)
            #pragma unroll
            for (int c = 0; c < 4; c++) acc[mt][nt][c] = 0.f;

    // ---- mainloop: 8 chunks of K=32 ----
    for (int kc = 0; kc < 8; kc++) {
        if (kc < 7) { load_B_chunk(sb, (kc + 1) & 1, kc + 1, tid); CP_COMMIT(); }
        uint32_t bstage = sb + OFF_B0 + (kc & 1) * B_STAGE;
        #pragma unroll
        for (int kk = 0; kk < 2; kk++) {        // two k16 steps per chunk
            int k0 = kc * 32 + kk * 16;
            uint32_t Ahi[2][4], Alo[2][4];
            LDSM4(Ahi[0], a_hi + k0 * 2);
            LDSM4(Ahi[1], a_hi + 16 * A_PITCH + k0 * 2);
            LDSM4(Alo[0], a_lo + k0 * 2);
            LDSM4(Alo[1], a_lo + 16 * A_PITCH + k0 * 2);
            uint32_t Bhi[4][4], Blo[4][4];
            uint32_t bk = bstage + kk * 16 * B_PITCH + b_off;
            #pragma unroll
            for (int p = 0; p < 4; p++) {
                LDSM4T(Bhi[p], bk + p * 32);
                LDSM4T(Blo[p], bk + B_MAT + p * 32);
            }
            #pragma unroll
            for (int mt = 0; mt < 2; mt++)
                #pragma unroll
                for (int p = 0; p < 4; p++) {
                    mma_bf16(acc[mt][2 * p],     Ahi[mt], &Bhi[p][0]);
                    mma_bf16(acc[mt][2 * p + 1], Ahi[mt], &Bhi[p][2]);
                    mma_bf16(acc[mt][2 * p],     Ahi[mt], &Blo[p][0]);
                    mma_bf16(acc[mt][2 * p + 1], Ahi[mt], &Blo[p][2]);
                    mma_bf16(acc[mt][2 * p],     Alo[mt], &Bhi[p][0]);
                    mma_bf16(acc[mt][2 * p + 1], Alo[mt], &Bhi[p][2]);
                }
        }
        if (kc < 7) CP_WAIT0();
        __syncthreads();
    }

    // ---- epilogue: gelu + layernorm + mask ----
    float* smB  = (float*)(smem + OFF_BIAS);
    float* smG  = (float*)(smem + OFF_G);
    float* smBe = (float*)(smem + OFF_BETA);
    float* ps   = (float*)(smem + OFF_PS);
    float* ps2  = (float*)(smem + OFF_PS2);

    float2 bia[8], gg[8], be[8];
    #pragma unroll
    for (int nt = 0; nt < 8; nt++) {
        int c = wn * 64 + nt * 8 + 2 * (lane & 3);
        bia[nt] = *(float2*)&smB[c];
        gg[nt]  = *(float2*)&smG[c];
        be[nt]  = *(float2*)&smBe[c];
    }

    // gelu in place + per-row partial sums
    #pragma unroll
    for (int mt = 0; mt < 2; mt++) {
        float sA = 0.f, s2A = 0.f, sB = 0.f, s2B = 0.f;
        #pragma unroll
        for (int nt = 0; nt < 8; nt++) {
            float v0 = gelu_exact(acc[mt][nt][0] + bia[nt].x);
            float v1 = gelu_exact(acc[mt][nt][1] + bia[nt].y);
            float v2 = gelu_exact(acc[mt][nt][2] + bia[nt].x);
            float v3 = gelu_exact(acc[mt][nt][3] + bia[nt].y);
            acc[mt][nt][0] = v0; acc[mt][nt][1] = v1;
            acc[mt][nt][2] = v2; acc[mt][nt][3] = v3;
            sA += v0 + v1; s2A += v0 * v0 + v1 * v1;
            sB += v2 + v3; s2B += v2 * v2 + v3 * v3;
        }
        #pragma unroll
        for (int o = 1; o <= 2; o <<= 1) {
            sA  += __shfl_xor_sync(0xFFFFFFFFu, sA,  o);
            s2A += __shfl_xor_sync(0xFFFFFFFFu, s2A, o);
            sB  += __shfl_xor_sync(0xFFFFFFFFu, sB,  o);
            s2B += __shfl_xor_sync(0xFFFFFFFFu, s2B, o);
        }
        if ((lane & 3) == 0) {
            int rA = wm * 32 + mt * 16 + (lane >> 2);
            ps[rA * 4 + wn]  = sA;  ps2[rA * 4 + wn]  = s2A;
            ps[(rA + 8) * 4 + wn] = sB; ps2[(rA + 8) * 4 + wn] = s2B;
        }
    }
    __syncthreads();

    #pragma unroll
    for (int mt = 0; mt < 2; mt++) {
        int rA = wm * 32 + mt * 16 + (lane >> 2);
        int rB = rA + 8;
        float tsA  = ps[rA * 4] + ps[rA * 4 + 1] + ps[rA * 4 + 2] + ps[rA * 4 + 3];
        float ts2A = ps2[rA * 4] + ps2[rA * 4 + 1] + ps2[rA * 4 + 2] + ps2[rA * 4 + 3];
        float tsB  = ps[rB * 4] + ps[rB * 4 + 1] + ps[rB * 4 + 2] + ps[rB * 4 + 3];
        float ts2B = ps2[rB * 4] + ps2[rB * 4 + 1] + ps2[rB * 4 + 2] + ps2[rB * 4 + 3];
        float muA = tsA * (1.f / 256.f);
        float muB = tsB * (1.f / 256.f);
        float invA = rsqrtf(ts2A * (1.f / 256.f) - muA * muA + 1e-5f);
        float invB = rsqrtf(ts2B * (1.f / 256.f) - muB * muB + 1e-5f);
        float mkA = tmask[m0 + rA];
        float mkB = tmask[m0 + rB];
        #pragma unroll
        for (int nt = 0; nt < 8; nt++) {
            int c = wn * 64 + nt * 8 + 2 * (lane & 3);
            float2 o1, o2;
            o1.x = ((acc[mt][nt][0] - muA) * invA * gg[nt].x + be[nt].x) * mkA;
            o1.y = ((acc[mt][nt][1] - muA) * invA * gg[nt].y + be[nt].y) * mkA;
            o2.x = ((acc[mt][nt][2] - muB) * invB * gg[nt].x + be[nt].x) * mkB;
            o2.y = ((acc[mt][nt][3] - muB) * invB * gg[nt].y + be[nt].y) * mkB;
            *(float2*)(out + (size_t)(m0 + rA) * DT + c) = o1;
            *(float2*)(out + (size_t)(m0 + rB) * DT + c) = o2;
        }
    }
}

// ---------------- launch ---------------------------------------------------
extern "C" void kernel_launch(void* const* d_in, const int* in_sizes, int n_in,
                              void* d_out, int out_size) {
    const float* student_emb = (const float*)d_in[0];
    const float* s_mask      = (const float*)d_in[1];
    const float* t_mask      = (const float*)d_in[2];
    int p = (in_sizes[3] == 64) ? 3 : 4;
    const float* pe_w1 = (const float*)d_in[p + 0];
    const float* pe_b1 = (const float*)d_in[p + 1];
    const float* pe_w2 = (const float*)d_in[p + 2];
    const float* pe_b2 = (const float*)d_in[p + 3];
    const float* pt_w  = (const float*)d_in[p + 4];
    const float* pt_b  = (const float*)d_in[p + 5];
    const float* ln_g  = (const float*)d_in[p + 6];
    const float* ln_b  = (const float*)d_in[p + 7];
    const float* nw    = (const float*)d_in[p + 8];
    float* out = (float*)d_out;

    cudaFuncSetAttribute(k_main, cudaFuncAttributeMaxDynamicSharedMemorySize, SMEM_TOTAL);

    k_prep<<<1, 1024>>>(s_mask, nw);
    k_posemb<<<T_, 128>>>(pe_w1, pe_b1, pe_w2, pe_b2);
    k_wsplit<<<DT * DT / 256, 256>>>(pt_w);
    k_main<<<NBLK, 256, SMEM_TOTAL>>>(student_emb, s_mask, t_mask,
                                      pt_b, ln_g, ln_b, out);
}

// round 4
// speedup vs baseline: 2.1795x; 1.2870x over previous
#include <cuda_runtime.h>
#include <cuda_bf16.h>
#include <cstdint>

#define B_   32
#define S_   4096
#define T_   8192
#define DIN  128
#define DT   256
#define M_   (B_ * T_)        // 262144
#define TILE_M 64
#define NBLK  (M_ / TILE_M)   // 4096

// ---------------- device-global tables (no runtime allocation) -------------
__device__ float    g_slens[B_];
__device__ float    g_w[4];
__device__ uint16_t g_whi[DT * DT];     // W bf16 hi, [k][n] row-major
__device__ uint16_t g_wlo[DT * DT];     // W bf16 lo
__device__ uint32_t g_pehi[T_ * 64];    // pos_emb packed bf16x2 hi, [t][pair]
__device__ uint32_t g_pelo[T_ * 64];

// ---------------- smem layout (swizzled, pitch 512) ------------------------
#define OFF_BIAS 0
#define OFF_G    1024
#define OFF_BETA 2048
#define OFF_PS   3072          // float[256]: psum[row][wn]
#define OFF_PS2  4096
#define OFF_A_HI 5120          // 64 rows x 512 B
#define OFF_A_LO (OFF_A_HI + 64 * 512)          // 37888
#define OFF_B0   (OFF_A_LO + 64 * 512)          // 70656
#define B_MAT    (16 * 512)                     // 8192 (one matrix, one K16 chunk)
#define B_STAGE  (2 * B_MAT)                    // hi + lo = 16384
#define SMEM_TOTAL (OFF_B0 + 2 * B_STAGE)       // 103424 -> 2 CTAs/SM

// ---------------- asm helpers ----------------------------------------------
__device__ __forceinline__ uint32_t smem_u32(const void* p) {
    uint32_t a;
    asm("{ .reg .u64 t; cvta.to.shared.u64 t, %1; cvt.u32.u64 %0, t; }" : "=r"(a) : "l"(p));
    return a;
}
#define CP_ASYNC16(dst, src) \
    asm volatile("cp.async.cg.shared.global [%0], [%1], 16;" :: "r"(dst), "l"(src))
#define CP_COMMIT() asm volatile("cp.async.commit_group;" ::: "memory")
#define CP_WAIT0()  asm volatile("cp.async.wait_group 0;" ::: "memory")

#define LDSM4(r, addr) \
    asm volatile("ldmatrix.sync.aligned.m8n8.x4.shared.b16 {%0,%1,%2,%3}, [%4];" \
        : "=r"((r)[0]), "=r"((r)[1]), "=r"((r)[2]), "=r"((r)[3]) : "r"(addr))
#define LDSM4T(r, addr) \
    asm volatile("ldmatrix.sync.aligned.m8n8.x4.trans.shared.b16 {%0,%1,%2,%3}, [%4];" \
        : "=r"((r)[0]), "=r"((r)[1]), "=r"((r)[2]), "=r"((r)[3]) : "r"(addr))

__device__ __forceinline__ void mma_bf16(float* c, const uint32_t* a, const uint32_t* b) {
    asm volatile("mma.sync.aligned.m16n8k16.row.col.f32.bf16.bf16.f32 "
        "{%0,%1,%2,%3}, {%4,%5,%6,%7}, {%8,%9}, {%0,%1,%2,%3};"
        : "+f"(c[0]), "+f"(c[1]), "+f"(c[2]), "+f"(c[3])
        : "r"(a[0]), "r"(a[1]), "r"(a[2]), "r"(a[3]), "r"(b[0]), "r"(b[1]));
}

// packs (x0 -> low half, x1 -> high half)
#define CVT2(result, x0, x1) \
    asm("cvt.rn.satfinite.bf16x2.f32 %0, %1, %2;" : "=r"(result) : "f"(x1), "f"(x0))

__device__ __forceinline__ float gelu_exact(float x) {
    return 0.5f * x * (1.0f + erff(x * 0.70710678118654752440f));
}

// ---------------- kernel 1: s_lens + neighbor softmax ----------------------
__global__ void k_prep(const float* __restrict__ s_mask, const float* __restrict__ nw) {
    int tid = threadIdx.x, w = tid >> 5, lane = tid & 31;
    const float* row = s_mask + (size_t)w * S_;
    float s = 0.f;
    for (int i = lane; i < S_; i += 32) s += row[i];
    #pragma unroll
    for (int o = 16; o; o >>= 1) s += __shfl_xor_sync(0xFFFFFFFFu, s, o);
    if (lane == 0) g_slens[w] = s;
    if (tid == 0) {
        float a = nw[0], b = nw[1], c = nw[2];
        float m = fmaxf(a, fmaxf(b, c));
        float ea = expf(a - m), eb = expf(b - m), ec = expf(c - m);
        float inv = 1.f / (ea + eb + ec);
        g_w[0] = ea * inv; g_w[1] = eb * inv; g_w[2] = ec * inv;
    }
}

// ---------------- kernel 2: pos_emb -> packed bf16x2 hi/lo [t][64] ---------
__global__ void k_posemb(const float* __restrict__ w1, const float* __restrict__ b1,
                         const float* __restrict__ w2, const float* __restrict__ b2) {
    __shared__ float h[64];
    int t = blockIdx.x, tid = threadIdx.x;   // 128 threads
    float pos = (float)t * (1.0f / (float)(T_ - 1));
    if (tid < 64) h[tid] = gelu_exact(pos * w1[tid] + b1[tid]);
    __syncthreads();
    float acc = b2[tid];
    #pragma unroll 16
    for (int j = 0; j < 64; j++) acc = fmaf(h[j], w2[j * DIN + tid], acc);
    float x1 = __shfl_down_sync(0xFFFFFFFFu, acc, 1);
    if ((tid & 1) == 0) {
        uint32_t ph; CVT2(ph, acc, x1);
        float l0 = acc - __uint_as_float(ph << 16);
        float l1 = x1  - __uint_as_float(ph & 0xFFFF0000u);
        uint32_t pl; CVT2(pl, l0, l1);
        g_pehi[t * 64 + (tid >> 1)] = ph;
        g_pelo[t * 64 + (tid >> 1)] = pl;
    }
}

// ---------------- kernel 3: W -> bf16 hi/lo [k][n] -------------------------
__global__ void k_wsplit(const float* __restrict__ W) {
    int idx = blockIdx.x * 256 + threadIdx.x;   // 65536
    float x = W[idx];
    __nv_bfloat16 hb = __float2bfloat16(x);
    float hf = __bfloat162float(hb);
    __nv_bfloat16 lb = __float2bfloat16(x - hf);
    __nv_bfloat16_raw hr = hb, lr = lb;
    g_whi[idx] = hr.x;
    g_wlo[idx] = lr.x;
}

// ---------------- B chunk loader: K=16, swizzled, cp.async -----------------
__device__ __forceinline__ void load_B_chunk(uint32_t sb, int stage, int chunk, int tid) {
    uint32_t dst = sb + OFF_B0 + stage * B_STAGE;
    const char* shi = (const char*)(g_whi + chunk * 16 * DT);
    const char* slo = (const char*)(g_wlo + chunk * 16 * DT);
    #pragma unroll
    for (int i = 0; i < 4; i++) {
        int f   = tid + 256 * i;           // 0..1023
        int mat = f >> 9;                  // 0=hi, 1=lo
        int r   = (f >> 5) & 15;           // K row within chunk
        int c   = f & 31;                  // 16B segment
        const char* src = (mat ? slo : shi) + (size_t)r * 512 + c * 16;
        CP_ASYNC16(dst + mat * B_MAT + r * 512 + ((c ^ (r & 7)) << 4), src);
    }
}

// ---------------- kernel 4: fused gather + bf16-split GEMM + epilogue ------
__global__ void __launch_bounds__(256, 2)
k_main(const float* __restrict__ emb, const float* __restrict__ s_mask,
       const float* __restrict__ tmask,
       const float* __restrict__ bias, const float* __restrict__ lng,
       const float* __restrict__ lnb, float* __restrict__ out) {
    extern __shared__ char smem[];
    uint32_t sb = smem_u32(smem);
    int tid = threadIdx.x, wid = tid >> 5, lane = tid & 31;
    int wm = wid >> 2;        // 0..1 : M half (32 rows)
    int wn = wid & 3;         // 0..3 : N quarter (64 cols)
    int m0 = blockIdx.x * TILE_M;
    int t0 = m0 & (T_ - 1);   // all 64 rows share batch b (T divisible by 64)
    int b  = m0 >> 13;

    // epilogue params to smem
    ((float*)(smem + OFF_BIAS))[tid] = bias[tid];
    ((float*)(smem + OFF_G))[tid]    = lng[tid];
    ((float*)(smem + OFF_BETA))[tid] = lnb[tid];

    // prefetch B chunk 0
    load_B_chunk(sb, 0, 0, tid);
    CP_COMMIT();

    // ---- produce A tile (64 x 256) in smem as bf16 hi/lo, swizzled --------
    {
        float slen = g_slens[b];
        float wv0 = g_w[0], wv1 = g_w[1], wv2 = g_w[2];
        const float* mrow = s_mask + (size_t)b * S_;
        #pragma unroll 2
        for (int i = 0; i < 8; i++) {
            int row = wid * 8 + i;
            int t = t0 + row;
            float pos = (float)t * (1.0f / (float)(T_ - 1));
            float sp  = pos * (slen - 1.0f);
            int curr = (int)sp;
            int prev = max(curr - 1, 0);
            int nxt  = min(curr + 1, S_ - 1);
            float w0 = wv0 * mrow[prev];
            float w1 = wv1 * mrow[curr];
            float w2 = wv2 * mrow[nxt];
            const float4* ep = (const float4*)(emb + ((size_t)b * S_ + prev) * DIN);
            const float4* ec = (const float4*)(emb + ((size_t)b * S_ + curr) * DIN);
            const float4* en = (const float4*)(emb + ((size_t)b * S_ + nxt)  * DIN);
            float4 vp = ep[lane], vc = ec[lane], vn = en[lane];
            float v0 = w0 * vp.x + w1 * vc.x + w2 * vn.x;
            float v1 = w0 * vp.y + w1 * vc.y + w2 * vn.y;
            float v2 = w0 * vp.z + w1 * vc.z + w2 * vn.z;
            float v3 = w0 * vp.w + w1 * vc.w + w2 * vn.w;
            uint32_t h0; CVT2(h0, v0, v1);
            uint32_t h1; CVT2(h1, v2, v3);
            float l00 = v0 - __uint_as_float(h0 << 16);
            float l01 = v1 - __uint_as_float(h0 & 0xFFFF0000u);
            float l10 = v2 - __uint_as_float(h1 << 16);
            float l11 = v3 - __uint_as_float(h1 & 0xFFFF0000u);
            uint32_t q0; CVT2(q0, l00, l01);
            uint32_t q1; CVT2(q1, l10, l11);
            uint32_t rbase = row * 512;
            uint32_t rxor  = (row & 7) << 4;
            // blended -> byte cols [8*lane .. 8*lane+7]
            uint32_t o1 = rbase + ((8 * lane) ^ rxor);
            *(uint2*)(smem + OFF_A_HI + o1) = make_uint2(h0, h1);
            *(uint2*)(smem + OFF_A_LO + o1) = make_uint2(q0, q1);
            // pos_emb -> byte cols [256 + 8*lane ...]
            uint2 peh = *(const uint2*)(g_pehi + (size_t)t * 64 + 2 * lane);
            uint2 pel = *(const uint2*)(g_pelo + (size_t)t * 64 + 2 * lane);
            uint32_t o2 = rbase + ((256 + 8 * lane) ^ rxor);
            *(uint2*)(smem + OFF_A_HI + o2) = peh;
            *(uint2*)(smem + OFF_A_LO + o2) = pel;
        }
    }

    // ---- ldmatrix lane addressing ----
    int xr = (lane & 7) + ((lane >> 3) & 1) * 8;   // 0..15
    int xg = lane >> 4;                            // 0..1
    int a_row = wm * 32 + xr;
    uint32_t a_base = sb + OFF_A_HI + a_row * 512;
    uint32_t a_xor  = ((a_row & 7) << 4) ^ (xg * 16);
    uint32_t b_base = xr * 512;                    // + col^bxor; + stage/mat
    uint32_t b_xor  = (xr & 7) << 4;
    int b_col = wn * 128 + xg * 16;                // byte col base for this lane

    float acc[2][8][4];
    #pragma unroll
    for (int mt = 0; mt < 2; mt++)
        #pragma unroll
        for (int nt = 0; nt < 8; nt++)
            #pragma unroll
            for (int c = 0; c < 4; c++) acc[mt][nt][c] = 0.f;

    // ---- mainloop: 16 chunks of K=16 ----
    for (int kc = 0; kc < 16; kc++) {
        CP_WAIT0();
        __syncthreads();
        if (kc < 15) { load_B_chunk(sb, (kc + 1) & 1, kc + 1, tid); CP_COMMIT(); }

        uint32_t bstage = sb + OFF_B0 + (kc & 1) * B_STAGE;
        uint32_t kbyte = (uint32_t)(kc * 32);       // k0*2
        uint32_t Ahi[2][4], Alo[2][4];
        LDSM4(Ahi[0], a_base + (kbyte ^ a_xor));
        LDSM4(Ahi[1], a_base + 16 * 512 + (kbyte ^ a_xor));
        LDSM4(Alo[0], a_base + (OFF_A_LO - OFF_A_HI) + (kbyte ^ a_xor));
        LDSM4(Alo[1], a_base + (OFF_A_LO - OFF_A_HI) + 16 * 512 + (kbyte ^ a_xor));
        #pragma unroll
        for (int p = 0; p < 4; p++) {
            uint32_t Bhi[4], Blo[4];
            uint32_t co = (uint32_t)(b_col + p * 32) ^ b_xor;
            LDSM4T(Bhi, bstage + b_base + co);
            LDSM4T(Blo, bstage + B_MAT + b_base + co);
            #pragma unroll
            for (int mt = 0; mt < 2; mt++) {
                mma_bf16(acc[mt][2 * p],     Ahi[mt], &Bhi[0]);
                mma_bf16(acc[mt][2 * p + 1], Ahi[mt], &Bhi[2]);
                mma_bf16(acc[mt][2 * p],     Ahi[mt], &Blo[0]);
                mma_bf16(acc[mt][2 * p + 1], Ahi[mt], &Blo[2]);
                mma_bf16(acc[mt][2 * p],     Alo[mt], &Bhi[0]);
                mma_bf16(acc[mt][2 * p + 1], Alo[mt], &Bhi[2]);
            }
        }
    }
    __syncthreads();

    // ---- epilogue: gelu + layernorm + mask ----
    float* smB  = (float*)(smem + OFF_BIAS);
    float* smG  = (float*)(smem + OFF_G);
    float* smBe = (float*)(smem + OFF_BETA);
    float* ps   = (float*)(smem + OFF_PS);
    float* ps2  = (float*)(smem + OFF_PS2);

    float2 bia[8], gg[8], be[8];
    #pragma unroll
    for (int nt = 0; nt < 8; nt++) {
        int c = wn * 64 + nt * 8 + 2 * (lane & 3);
        bia[nt] = *(float2*)&smB[c];
        gg[nt]  = *(float2*)&smG[c];
        be[nt]  = *(float2*)&smBe[c];
    }

    #pragma unroll
    for (int mt = 0; mt < 2; mt++) {
        float sA = 0.f, s2A = 0.f, sB = 0.f, s2B = 0.f;
        #pragma unroll
        for (int nt = 0; nt < 8; nt++) {
            float v0 = gelu_exact(acc[mt][nt][0] + bia[nt].x);
            float v1 = gelu_exact(acc[mt][nt][1] + bia[nt].y);
            float v2 = gelu_exact(acc[mt][nt][2] + bia[nt].x);
            float v3 = gelu_exact(acc[mt][nt][3] + bia[nt].y);
            acc[mt][nt][0] = v0; acc[mt][nt][1] = v1;
            acc[mt][nt][2] = v2; acc[mt][nt][3] = v3;
            sA += v0 + v1; s2A += v0 * v0 + v1 * v1;
            sB += v2 + v3; s2B += v2 * v2 + v3 * v3;
        }
        #pragma unroll
        for (int o = 1; o <= 2; o <<= 1) {
            sA  += __shfl_xor_sync(0xFFFFFFFFu, sA,  o);
            s2A += __shfl_xor_sync(0xFFFFFFFFu, s2A, o);
            sB  += __shfl_xor_sync(0xFFFFFFFFu, sB,  o);
            s2B += __shfl_xor_sync(0xFFFFFFFFu, s2B, o);
        }
        if ((lane & 3) == 0) {
            int rA = wm * 32 + mt * 16 + (lane >> 2);
            ps[rA * 4 + wn]  = sA;  ps2[rA * 4 + wn]  = s2A;
            ps[(rA + 8) * 4 + wn] = sB; ps2[(rA + 8) * 4 + wn] = s2B;
        }
    }
    __syncthreads();

    #pragma unroll
    for (int mt = 0; mt < 2; mt++) {
        int rA = wm * 32 + mt * 16 + (lane >> 2);
        int rB = rA + 8;
        float tsA  = ps[rA * 4] + ps[rA * 4 + 1] + ps[rA * 4 + 2] + ps[rA * 4 + 3];
        float ts2A = ps2[rA * 4] + ps2[rA * 4 + 1] + ps2[rA * 4 + 2] + ps2[rA * 4 + 3];
        float tsB  = ps[rB * 4] + ps[rB * 4 + 1] + ps[rB * 4 + 2] + ps[rB * 4 + 3];
        float ts2B = ps2[rB * 4] + ps2[rB * 4 + 1] + ps2[rB * 4 + 2] + ps2[rB * 4 + 3];
        float muA = tsA * (1.f / 256.f);
        float muB = tsB * (1.f / 256.f);
        float invA = rsqrtf(ts2A * (1.f / 256.f) - muA * muA + 1e-5f);
        float invB = rsqrtf(ts2B * (1.f / 256.f) - muB * muB + 1e-5f);
        float mkA = tmask[m0 + rA];
        float mkB = tmask[m0 + rB];
        #pragma unroll
        for (int nt = 0; nt < 8; nt++) {
            int c = wn * 64 + nt * 8 + 2 * (lane & 3);
            float2 o1, o2;
            o1.x = ((acc[mt][nt][0] - muA) * invA * gg[nt].x + be[nt].x) * mkA;
            o1.y = ((acc[mt][nt][1] - muA) * invA * gg[nt].y + be[nt].y) * mkA;
            o2.x = ((acc[mt][nt][2] - muB) * invB * gg[nt].x + be[nt].x) * mkB;
            o2.y = ((acc[mt][nt][3] - muB) * invB * gg[nt].y + be[nt].y) * mkB;
            *(float2*)(out + (size_t)(m0 + rA) * DT + c) = o1;
            *(float2*)(out + (size_t)(m0 + rB) * DT + c) = o2;
        }
    }
}

// ---------------- launch ---------------------------------------------------
extern "C" void kernel_launch(void* const* d_in, const int* in_sizes, int n_in,
                              void* d_out, int out_size) {
    const float* student_emb = (const float*)d_in[0];
    const float* s_mask      = (const float*)d_in[1];
    const float* t_mask      = (const float*)d_in[2];
    int p = (in_sizes[3] == 64) ? 3 : 4;
    const float* pe_w1 = (const float*)d_in[p + 0];
    const float* pe_b1 = (const float*)d_in[p + 1];
    const float* pe_w2 = (const float*)d_in[p + 2];
    const float* pe_b2 = (const float*)d_in[p + 3];
    const float* pt_w  = (const float*)d_in[p + 4];
    const float* pt_b  = (const float*)d_in[p + 5];
    const float* ln_g  = (const float*)d_in[p + 6];
    const float* ln_b  = (const float*)d_in[p + 7];
    const float* nw    = (const float*)d_in[p + 8];
    float* out = (float*)d_out;

    cudaFuncSetAttribute(k_main, cudaFuncAttributeMaxDynamicSharedMemorySize, SMEM_TOTAL);

    k_prep<<<1, 1024>>>(s_mask, nw);
    k_posemb<<<T_, 128>>>(pe_w1, pe_b1, pe_w2, pe_b2);
    k_wsplit<<<DT * DT / 256, 256>>>(pt_w);
    k_main<<<NBLK, 256, SMEM_TOTAL>>>(student_emb, s_mask, t_mask,
                                      pt_b, ln_g, ln_b, out);
}

// round 5
// speedup vs baseline: 2.2479x; 1.0314x over previous
#include <cuda_runtime.h>
#include <cuda_bf16.h>
#include <cstdint>

#define B_   32
#define S_   4096
#define T_   8192
#define DIN  128
#define DT   256
#define M_   (B_ * T_)        // 262144
#define TILE_M 64
#define NBLK  (M_ / TILE_M)   // 4096

// ---------------- device-global tables (no runtime allocation) -------------
__device__ float    g_slens[B_];
__device__ float    g_w[4];
__device__ uint16_t g_whi[DT * DT];     // W bf16 hi, [k][n] row-major
__device__ uint16_t g_wlo[DT * DT];     // W bf16 lo
__device__ uint32_t g_pehi[T_ * 64];    // pos_emb packed bf16x2 hi, [t][pair]
__device__ uint32_t g_pelo[T_ * 64];

// ---------------- smem layout (swizzled, pitch 512) ------------------------
#define OFF_A_HI 0              // 64 rows x 512 B
#define OFF_A_LO 32768
#define OFF_B0   65536
#define B_MAT    8192           // 16 rows x 512 (one matrix, one K16 chunk)
#define B_STAGE  16384          // hi + lo
#define SMEM_TOTAL (OFF_B0 + 3 * B_STAGE)   // 114688 -> 2 CTAs/SM
// epilogue overlays (valid after final mainloop barrier):
#define OFF_PS   OFF_B0
#define OFF_PS2  (OFF_B0 + 1024)

// ---------------- asm helpers ----------------------------------------------
__device__ __forceinline__ uint32_t smem_u32(const void* p) {
    uint32_t a;
    asm("{ .reg .u64 t; cvta.to.shared.u64 t, %1; cvt.u32.u64 %0, t; }" : "=r"(a) : "l"(p));
    return a;
}
#define CP_ASYNC16(dst, src) \
    asm volatile("cp.async.cg.shared.global [%0], [%1], 16;" :: "r"(dst), "l"(src))
#define CP_COMMIT() asm volatile("cp.async.commit_group;" ::: "memory")
#define CP_WAIT0()  asm volatile("cp.async.wait_group 0;" ::: "memory")
#define CP_WAIT1()  asm volatile("cp.async.wait_group 1;" ::: "memory")

#define LDSM4(r, addr) \
    asm volatile("ldmatrix.sync.aligned.m8n8.x4.shared.b16 {%0,%1,%2,%3}, [%4];" \
        : "=r"((r)[0]), "=r"((r)[1]), "=r"((r)[2]), "=r"((r)[3]) : "r"(addr))
#define LDSM4T(r, addr) \
    asm volatile("ldmatrix.sync.aligned.m8n8.x4.trans.shared.b16 {%0,%1,%2,%3}, [%4];" \
        : "=r"((r)[0]), "=r"((r)[1]), "=r"((r)[2]), "=r"((r)[3]) : "r"(addr))

// NOTE: not volatile -> ptxas is free to schedule/pipeline MMAs.
__device__ __forceinline__ void mma_bf16(float* c, const uint32_t* a, const uint32_t* b) {
    asm("mma.sync.aligned.m16n8k16.row.col.f32.bf16.bf16.f32 "
        "{%0,%1,%2,%3}, {%4,%5,%6,%7}, {%8,%9}, {%0,%1,%2,%3};"
        : "+f"(c[0]), "+f"(c[1]), "+f"(c[2]), "+f"(c[3])
        : "r"(a[0]), "r"(a[1]), "r"(a[2]), "r"(a[3]), "r"(b[0]), "r"(b[1]));
}

// packs (x0 -> low half, x1 -> high half)
#define CVT2(result, x0, x1) \
    asm("cvt.rn.satfinite.bf16x2.f32 %0, %1, %2;" : "=r"(result) : "f"(x1), "f"(x0))

__device__ __forceinline__ float gelu_exact(float x) {
    return 0.5f * x * (1.0f + erff(x * 0.70710678118654752440f));
}

// ---------------- kernel 1: s_lens + neighbor softmax ----------------------
__global__ void k_prep(const float* __restrict__ s_mask, const float* __restrict__ nw) {
    int tid = threadIdx.x, w = tid >> 5, lane = tid & 31;
    const float* row = s_mask + (size_t)w * S_;
    float s = 0.f;
    for (int i = lane; i < S_; i += 32) s += row[i];
    #pragma unroll
    for (int o = 16; o; o >>= 1) s += __shfl_xor_sync(0xFFFFFFFFu, s, o);
    if (lane == 0) g_slens[w] = s;
    if (tid == 0) {
        float a = nw[0], b = nw[1], c = nw[2];
        float m = fmaxf(a, fmaxf(b, c));
        float ea = expf(a - m), eb = expf(b - m), ec = expf(c - m);
        float inv = 1.f / (ea + eb + ec);
        g_w[0] = ea * inv; g_w[1] = eb * inv; g_w[2] = ec * inv;
    }
}

// ---------------- kernel 2: pos_emb -> packed bf16x2 hi/lo [t][64] ---------
__global__ void k_posemb(const float* __restrict__ w1, const float* __restrict__ b1,
                         const float* __restrict__ w2, const float* __restrict__ b2) {
    __shared__ float h[64];
    int t = blockIdx.x, tid = threadIdx.x;   // 128 threads
    float pos = (float)t * (1.0f / (float)(T_ - 1));
    if (tid < 64) h[tid] = gelu_exact(pos * w1[tid] + b1[tid]);
    __syncthreads();
    float acc = b2[tid];
    #pragma unroll 16
    for (int j = 0; j < 64; j++) acc = fmaf(h[j], w2[j * DIN + tid], acc);
    float x1 = __shfl_down_sync(0xFFFFFFFFu, acc, 1);
    if ((tid & 1) == 0) {
        uint32_t ph; CVT2(ph, acc, x1);
        float l0 = acc - __uint_as_float(ph << 16);
        float l1 = x1  - __uint_as_float(ph & 0xFFFF0000u);
        uint32_t pl; CVT2(pl, l0, l1);
        g_pehi[t * 64 + (tid >> 1)] = ph;
        g_pelo[t * 64 + (tid >> 1)] = pl;
    }
}

// ---------------- kernel 3: W -> bf16 hi/lo [k][n] -------------------------
__global__ void k_wsplit(const float* __restrict__ W) {
    int idx = blockIdx.x * 256 + threadIdx.x;   // 65536
    float x = W[idx];
    __nv_bfloat16 hb = __float2bfloat16(x);
    float hf = __bfloat162float(hb);
    __nv_bfloat16 lb = __float2bfloat16(x - hf);
    __nv_bfloat16_raw hr = hb, lr = lb;
    g_whi[idx] = hr.x;
    g_wlo[idx] = lr.x;
}

// ---------------- B chunk loader: K=16, swizzled, cp.async -----------------
__device__ __forceinline__ void load_B_chunk(uint32_t sb, int stage, int chunk, int tid) {
    uint32_t dst = sb + OFF_B0 + stage * B_STAGE;
    const char* shi = (const char*)(g_whi + chunk * 16 * DT);
    const char* slo = (const char*)(g_wlo + chunk * 16 * DT);
    #pragma unroll
    for (int i = 0; i < 4; i++) {
        int f   = tid + 256 * i;           // 0..1023
        int mat = f >> 9;                  // 0=hi, 1=lo
        int r   = (f >> 5) & 15;           // K row within chunk
        int c   = f & 31;                  // 16B segment
        const char* src = (mat ? slo : shi) + (size_t)r * 512 + c * 16;
        CP_ASYNC16(dst + mat * B_MAT + r * 512 + ((c ^ (r & 7)) << 4), src);
    }
}

// ---------------- kernel 4: fused gather + bf16-split GEMM + epilogue ------
__global__ void __launch_bounds__(256, 2)
k_main(const float* __restrict__ emb, const float* __restrict__ s_mask,
       const float* __restrict__ tmask,
       const float* __restrict__ bias, const float* __restrict__ lng,
       const float* __restrict__ lnb, float* __restrict__ out) {
    extern __shared__ char smem[];
    uint32_t sb = smem_u32(smem);
    int tid = threadIdx.x, wid = tid >> 5, lane = tid & 31;
    int wm = wid >> 2;        // 0..1 : M half (32 rows)
    int wn = wid & 3;         // 0..3 : N quarter (64 cols)
    int m0 = blockIdx.x * TILE_M;
    int t0 = m0 & (T_ - 1);   // all 64 rows share batch b (T divisible by 64)
    int b  = m0 >> 13;

    // prefetch B chunks 0,1 (stages 0,1)
    load_B_chunk(sb, 0, 0, tid);
    CP_COMMIT();
    load_B_chunk(sb, 1, 1, tid);
    CP_COMMIT();

    // ---- produce A tile (64 x 256) in smem as bf16 hi/lo, swizzled --------
    {
        float slen = g_slens[b];
        float wv0 = g_w[0], wv1 = g_w[1], wv2 = g_w[2];
        const float* mrow = s_mask + (size_t)b * S_;
        #pragma unroll 2
        for (int i = 0; i < 8; i++) {
            int row = wid * 8 + i;
            int t = t0 + row;
            float pos = (float)t * (1.0f / (float)(T_ - 1));
            float sp  = pos * (slen - 1.0f);
            int curr = (int)sp;
            int prev = max(curr - 1, 0);
            int nxt  = min(curr + 1, S_ - 1);
            float w0 = wv0 * mrow[prev];
            float w1 = wv1 * mrow[curr];
            float w2 = wv2 * mrow[nxt];
            const float4* ep = (const float4*)(emb + ((size_t)b * S_ + prev) * DIN);
            const float4* ec = (const float4*)(emb + ((size_t)b * S_ + curr) * DIN);
            const float4* en = (const float4*)(emb + ((size_t)b * S_ + nxt)  * DIN);
            float4 vp = ep[lane], vc = ec[lane], vn = en[lane];
            float v0 = w0 * vp.x + w1 * vc.x + w2 * vn.x;
            float v1 = w0 * vp.y + w1 * vc.y + w2 * vn.y;
            float v2 = w0 * vp.z + w1 * vc.z + w2 * vn.z;
            float v3 = w0 * vp.w + w1 * vc.w + w2 * vn.w;
            uint32_t h0; CVT2(h0, v0, v1);
            uint32_t h1; CVT2(h1, v2, v3);
            float l00 = v0 - __uint_as_float(h0 << 16);
            float l01 = v1 - __uint_as_float(h0 & 0xFFFF0000u);
            float l10 = v2 - __uint_as_float(h1 << 16);
            float l11 = v3 - __uint_as_float(h1 & 0xFFFF0000u);
            uint32_t q0; CVT2(q0, l00, l01);
            uint32_t q1; CVT2(q1, l10, l11);
            uint32_t rbase = row * 512;
            uint32_t rxor  = (row & 7) << 4;
            uint32_t o1 = rbase + ((8 * lane) ^ rxor);
            *(uint2*)(smem + OFF_A_HI + o1) = make_uint2(h0, h1);
            *(uint2*)(smem + OFF_A_LO + o1) = make_uint2(q0, q1);
            uint2 peh = *(const uint2*)(g_pehi + (size_t)t * 64 + 2 * lane);
            uint2 pel = *(const uint2*)(g_pelo + (size_t)t * 64 + 2 * lane);
            uint32_t o2 = rbase + ((256 + 8 * lane) ^ rxor);
            *(uint2*)(smem + OFF_A_HI + o2) = peh;
            *(uint2*)(smem + OFF_A_LO + o2) = pel;
        }
    }

    // ---- ldmatrix lane addressing ----
    int xr = (lane & 7) + ((lane >> 3) & 1) * 8;   // 0..15
    int xg = lane >> 4;                            // 0..1
    int a_row = wm * 32 + xr;
    uint32_t a_base = sb + OFF_A_HI + a_row * 512;
    uint32_t a_xor  = ((a_row & 7) << 4) ^ (xg * 16);
    uint32_t b_base = xr * 512;
    uint32_t b_xor  = (xr & 7) << 4;
    int b_col = wn * 128 + xg * 16;                // byte col base for this lane
    uint32_t co[4];
    #pragma unroll
    for (int p = 0; p < 4; p++) co[p] = ((uint32_t)(b_col + p * 32) ^ b_xor) + b_base;

    float acc[2][8][4];
    #pragma unroll
    for (int mt = 0; mt < 2; mt++)
        #pragma unroll
        for (int nt = 0; nt < 8; nt++)
            #pragma unroll
            for (int c = 0; c < 4; c++) acc[mt][nt][c] = 0.f;

    // ---- mainloop: 16 chunks of K=16, 3-stage pipeline --------------------
    int st = 0;
    for (int kc = 0; kc < 16; kc++) {
        if (kc == 15) { CP_WAIT0(); } else { CP_WAIT1(); }
        __syncthreads();
        if (kc < 14) {
            int nst = st + 2; if (nst >= 3) nst -= 3;
            load_B_chunk(sb, nst, kc + 2, tid);
            CP_COMMIT();
        }
        uint32_t bstage = sb + OFF_B0 + st * B_STAGE;
        uint32_t aoff = ((uint32_t)(kc * 32)) ^ a_xor;
        uint32_t Ahi[2][4], Alo[2][4];
        LDSM4(Ahi[0], a_base + aoff);
        LDSM4(Ahi[1], a_base + 16 * 512 + aoff);
        LDSM4(Alo[0], a_base + (OFF_A_LO - OFF_A_HI) + aoff);
        LDSM4(Alo[1], a_base + (OFF_A_LO - OFF_A_HI) + 16 * 512 + aoff);
        #pragma unroll
        for (int p = 0; p < 4; p++) {
            uint32_t Bhi[4], Blo[4];
            LDSM4T(Bhi, bstage + co[p]);
            LDSM4T(Blo, bstage + B_MAT + co[p]);
            // product-major: dependent MMAs on same acc are 4 apart
            mma_bf16(acc[0][2 * p],     Ahi[0], &Bhi[0]);
            mma_bf16(acc[0][2 * p + 1], Ahi[0], &Bhi[2]);
            mma_bf16(acc[1][2 * p],     Ahi[1], &Bhi[0]);
            mma_bf16(acc[1][2 * p + 1], Ahi[1], &Bhi[2]);
            mma_bf16(acc[0][2 * p],     Ahi[0], &Blo[0]);
            mma_bf16(acc[0][2 * p + 1], Ahi[0], &Blo[2]);
            mma_bf16(acc[1][2 * p],     Ahi[1], &Blo[0]);
            mma_bf16(acc[1][2 * p + 1], Ahi[1], &Blo[2]);
            mma_bf16(acc[0][2 * p],     Alo[0], &Bhi[0]);
            mma_bf16(acc[0][2 * p + 1], Alo[0], &Bhi[2]);
            mma_bf16(acc[1][2 * p],     Alo[1], &Bhi[0]);
            mma_bf16(acc[1][2 * p + 1], Alo[1], &Bhi[2]);
        }
        st = (st == 2) ? 0 : st + 1;
    }
    __syncthreads();   // frees B smem region for LN partial overlay

    // ---- epilogue: gelu + layernorm + mask (params straight from gmem) ----
    float* ps   = (float*)(smem + OFF_PS);
    float* ps2  = (float*)(smem + OFF_PS2);

    float2 bia[8], gg[8], be[8];
    #pragma unroll
    for (int nt = 0; nt < 8; nt++) {
        int c = wn * 64 + nt * 8 + 2 * (lane & 3);
        bia[nt] = *(const float2*)&bias[c];
        gg[nt]  = *(const float2*)&lng[c];
        be[nt]  = *(const float2*)&lnb[c];
    }

    #pragma unroll
    for (int mt = 0; mt < 2; mt++) {
        float sA = 0.f, s2A = 0.f, sB = 0.f, s2B = 0.f;
        #pragma unroll
        for (int nt = 0; nt < 8; nt++) {
            float v0 = gelu_exact(acc[mt][nt][0] + bia[nt].x);
            float v1 = gelu_exact(acc[mt][nt][1] + bia[nt].y);
            float v2 = gelu_exact(acc[mt][nt][2] + bia[nt].x);
            float v3 = gelu_exact(acc[mt][nt][3] + bia[nt].y);
            acc[mt][nt][0] = v0; acc[mt][nt][1] = v1;
            acc[mt][nt][2] = v2; acc[mt][nt][3] = v3;
            sA += v0 + v1; s2A += v0 * v0 + v1 * v1;
            sB += v2 + v3; s2B += v2 * v2 + v3 * v3;
        }
        #pragma unroll
        for (int o = 1; o <= 2; o <<= 1) {
            sA  += __shfl_xor_sync(0xFFFFFFFFu, sA,  o);
            s2A += __shfl_xor_sync(0xFFFFFFFFu, s2A, o);
            sB  += __shfl_xor_sync(0xFFFFFFFFu, sB,  o);
            s2B += __shfl_xor_sync(0xFFFFFFFFu, s2B, o);
        }
        if ((lane & 3) == 0) {
            int rA = wm * 32 + mt * 16 + (lane >> 2);
            ps[rA * 4 + wn]  = sA;  ps2[rA * 4 + wn]  = s2A;
            ps[(rA + 8) * 4 + wn] = sB; ps2[(rA + 8) * 4 + wn] = s2B;
        }
    }
    __syncthreads();

    #pragma unroll
    for (int mt = 0; mt < 2; mt++) {
        int rA = wm * 32 + mt * 16 + (lane >> 2);
        int rB = rA + 8;
        float tsA  = ps[rA * 4] + ps[rA * 4 + 1] + ps[rA * 4 + 2] + ps[rA * 4 + 3];
        float ts2A = ps2[rA * 4] + ps2[rA * 4 + 1] + ps2[rA * 4 + 2] + ps2[rA * 4 + 3];
        float tsB  = ps[rB * 4] + ps[rB * 4 + 1] + ps[rB * 4 + 2] + ps[rB * 4 + 3];
        float ts2B = ps2[rB * 4] + ps2[rB * 4 + 1] + ps2[rB * 4 + 2] + ps2[rB * 4 + 3];
        float muA = tsA * (1.f / 256.f);
        float muB = tsB * (1.f / 256.f);
        float invA = rsqrtf(ts2A * (1.f / 256.f) - muA * muA + 1e-5f);
        float invB = rsqrtf(ts2B * (1.f / 256.f) - muB * muB + 1e-5f);
        float mkA = tmask[m0 + rA];
        float mkB = tmask[m0 + rB];
        #pragma unroll
        for (int nt = 0; nt < 8; nt++) {
            int c = wn * 64 + nt * 8 + 2 * (lane & 3);
            float2 o1, o2;
            o1.x = ((acc[mt][nt][0] - muA) * invA * gg[nt].x + be[nt].x) * mkA;
            o1.y = ((acc[mt][nt][1] - muA) * invA * gg[nt].y + be[nt].y) * mkA;
            o2.x = ((acc[mt][nt][2] - muB) * invB * gg[nt].x + be[nt].x) * mkB;
            o2.y = ((acc[mt][nt][3] - muB) * invB * gg[nt].y + be[nt].y) * mkB;
            *(float2*)(out + (size_t)(m0 + rA) * DT + c) = o1;
            *(float2*)(out + (size_t)(m0 + rB) * DT + c) = o2;
        }
    }
}

// ---------------- launch ---------------------------------------------------
extern "C" void kernel_launch(void* const* d_in, const int* in_sizes, int n_in,
                              void* d_out, int out_size) {
    const float* student_emb = (const float*)d_in[0];
    const float* s_mask      = (const float*)d_in[1];
    const float* t_mask      = (const float*)d_in[2];
    int p = (in_sizes[3] == 64) ? 3 : 4;
    const float* pe_w1 = (const float*)d_in[p + 0];
    const float* pe_b1 = (const float*)d_in[p + 1];
    const float* pe_w2 = (const float*)d_in[p + 2];
    const float* pe_b2 = (const float*)d_in[p + 3];
    const float* pt_w  = (const float*)d_in[p + 4];
    const float* pt_b  = (const float*)d_in[p + 5];
    const float* ln_g  = (const float*)d_in[p + 6];
    const float* ln_b  = (const float*)d_in[p + 7];
    const float* nw    = (const float*)d_in[p + 8];
    float* out = (float*)d_out;

    cudaFuncSetAttribute(k_main, cudaFuncAttributeMaxDynamicSharedMemorySize, SMEM_TOTAL);

    k_prep<<<1, 1024>>>(s_mask, nw);
    k_posemb<<<T_, 128>>>(pe_w1, pe_b1, pe_w2, pe_b2);
    k_wsplit<<<DT * DT / 256, 256>>>(pt_w);
    k_main<<<NBLK, 256, SMEM_TOTAL>>>(student_emb, s_mask, t_mask,
                                      pt_b, ln_g, ln_b, out);
}

// round 6
// speedup vs baseline: 2.6469x; 1.1775x over previous
#include <cuda_runtime.h>
#include <cuda_bf16.h>
#include <cstdint>

#define B_   32
#define S_   4096
#define T_   8192
#define DIN  128
#define DT   256
#define M_   (B_ * T_)        // 262144
#define TILE_M 64
#define NBLK  (M_ / TILE_M)   // 4096

// ---------------- device-global tables (no runtime allocation) -------------
__device__ float    g_slens[B_];
__device__ float    g_w[4];
__device__ uint16_t g_whi[DT * DT];     // W bf16 hi, [k][n] row-major
__device__ uint16_t g_wlo[DT * DT];     // W bf16 lo
__device__ uint32_t g_pehi[T_ * 64];    // pos_emb packed bf16x2 hi, [t][pair]
__device__ uint32_t g_pelo[T_ * 64];

// ---------------- smem layout (swizzled, pitch 512) ------------------------
#define OFF_A_HI 0              // 64 rows x 512 B
#define OFF_A_LO 32768
#define OFF_B0   65536
#define B_MAT    8192           // 16 rows x 512 (one matrix, one K16 chunk)
#define B_STAGE  16384          // hi + lo
#define SMEM_TOTAL (OFF_B0 + 3 * B_STAGE)   // 114688 -> 2 CTAs/SM
// epilogue overlays (valid after final mainloop barrier):
#define OFF_PS   OFF_B0
#define OFF_PS2  (OFF_B0 + 1024)

// ---------------- asm helpers ----------------------------------------------
__device__ __forceinline__ uint32_t smem_u32(const void* p) {
    uint32_t a;
    asm("{ .reg .u64 t; cvta.to.shared.u64 t, %1; cvt.u32.u64 %0, t; }" : "=r"(a) : "l"(p));
    return a;
}
#define CP_ASYNC16(dst, src) \
    asm volatile("cp.async.cg.shared.global [%0], [%1], 16;" :: "r"(dst), "l"(src))
#define CP_COMMIT() asm volatile("cp.async.commit_group;" ::: "memory")
#define CP_WAIT0()  asm volatile("cp.async.wait_group 0;" ::: "memory")
#define CP_WAIT1()  asm volatile("cp.async.wait_group 1;" ::: "memory")

#define LDSM4(r, addr) \
    asm volatile("ldmatrix.sync.aligned.m8n8.x4.shared.b16 {%0,%1,%2,%3}, [%4];" \
        : "=r"((r)[0]), "=r"((r)[1]), "=r"((r)[2]), "=r"((r)[3]) : "r"(addr))
#define LDSM4T(r, addr) \
    asm volatile("ldmatrix.sync.aligned.m8n8.x4.trans.shared.b16 {%0,%1,%2,%3}, [%4];" \
        : "=r"((r)[0]), "=r"((r)[1]), "=r"((r)[2]), "=r"((r)[3]) : "r"(addr))

// NOTE: not volatile -> ptxas is free to schedule/pipeline MMAs.
__device__ __forceinline__ void mma_bf16(float* c, const uint32_t* a, const uint32_t* b) {
    asm("mma.sync.aligned.m16n8k16.row.col.f32.bf16.bf16.f32 "
        "{%0,%1,%2,%3}, {%4,%5,%6,%7}, {%8,%9}, {%0,%1,%2,%3};"
        : "+f"(c[0]), "+f"(c[1]), "+f"(c[2]), "+f"(c[3])
        : "r"(a[0]), "r"(a[1]), "r"(a[2]), "r"(a[3]), "r"(b[0]), "r"(b[1]));
}

// packs (x0 -> low half, x1 -> high half)
#define CVT2(result, x0, x1) \
    asm("cvt.rn.satfinite.bf16x2.f32 %0, %1, %2;" : "=r"(result) : "f"(x1), "f"(x0))

__device__ __forceinline__ float gelu_exact(float x) {
    return 0.5f * x * (1.0f + erff(x * 0.70710678118654752440f));
}

// ---------------- kernel 1: s_lens + neighbor softmax ----------------------
__global__ void k_prep(const float* __restrict__ s_mask, const float* __restrict__ nw) {
    int tid = threadIdx.x, w = tid >> 5, lane = tid & 31;
    const float* row = s_mask + (size_t)w * S_;
    float s = 0.f;
    for (int i = lane; i < S_; i += 32) s += row[i];
    #pragma unroll
    for (int o = 16; o; o >>= 1) s += __shfl_xor_sync(0xFFFFFFFFu, s, o);
    if (lane == 0) g_slens[w] = s;
    if (tid == 0) {
        float a = nw[0], b = nw[1], c = nw[2];
        float m = fmaxf(a, fmaxf(b, c));
        float ea = expf(a - m), eb = expf(b - m), ec = expf(c - m);
        float inv = 1.f / (ea + eb + ec);
        g_w[0] = ea * inv; g_w[1] = eb * inv; g_w[2] = ec * inv;
    }
}

// ---------------- kernel 2: pos_emb -> packed bf16x2 hi/lo [t][64] ---------
__global__ void k_posemb(const float* __restrict__ w1, const float* __restrict__ b1,
                         const float* __restrict__ w2, const float* __restrict__ b2) {
    __shared__ float h[64];
    int t = blockIdx.x, tid = threadIdx.x;   // 128 threads
    float pos = (float)t * (1.0f / (float)(T_ - 1));
    if (tid < 64) h[tid] = gelu_exact(pos * w1[tid] + b1[tid]);
    __syncthreads();
    float acc = b2[tid];
    #pragma unroll 16
    for (int j = 0; j < 64; j++) acc = fmaf(h[j], w2[j * DIN + tid], acc);
    float x1 = __shfl_down_sync(0xFFFFFFFFu, acc, 1);
    if ((tid & 1) == 0) {
        uint32_t ph; CVT2(ph, acc, x1);
        float l0 = acc - __uint_as_float(ph << 16);
        float l1 = x1  - __uint_as_float(ph & 0xFFFF0000u);
        uint32_t pl; CVT2(pl, l0, l1);
        g_pehi[t * 64 + (tid >> 1)] = ph;
        g_pelo[t * 64 + (tid >> 1)] = pl;
    }
}

// ---------------- kernel 3: W -> bf16 hi/lo [k][n] -------------------------
__global__ void k_wsplit(const float* __restrict__ W) {
    int idx = blockIdx.x * 256 + threadIdx.x;   // 65536
    float x = W[idx];
    __nv_bfloat16 hb = __float2bfloat16(x);
    float hf = __bfloat162float(hb);
    __nv_bfloat16 lb = __float2bfloat16(x - hf);
    __nv_bfloat16_raw hr = hb, lr = lb;
    g_whi[idx] = hr.x;
    g_wlo[idx] = lr.x;
}

// ---------------- B chunk loader: K=16, swizzled, cp.async -----------------
__device__ __forceinline__ void load_B_chunk(uint32_t sb, int stage, int chunk, int tid) {
    uint32_t dst = sb + OFF_B0 + stage * B_STAGE;
    const char* shi = (const char*)(g_whi + chunk * 16 * DT);
    const char* slo = (const char*)(g_wlo + chunk * 16 * DT);
    #pragma unroll
    for (int i = 0; i < 4; i++) {
        int f   = tid + 256 * i;           // 0..1023
        int mat = f >> 9;                  // 0=hi, 1=lo
        int r   = (f >> 5) & 15;           // K row within chunk
        int c   = f & 31;                  // 16B segment
        const char* src = (mat ? slo : shi) + (size_t)r * 512 + c * 16;
        CP_ASYNC16(dst + mat * B_MAT + r * 512 + ((c ^ (r & 7)) << 4), src);
    }
}

// ---------------- kernel 4: fused gather + bf16-split GEMM + epilogue ------
__global__ void __launch_bounds__(256, 2)
k_main(const float* __restrict__ emb, const float* __restrict__ s_mask,
       const float* __restrict__ tmask,
       const float* __restrict__ bias, const float* __restrict__ lng,
       const float* __restrict__ lnb, float* __restrict__ out) {
    extern __shared__ char smem[];
    uint32_t sb = smem_u32(smem);
    int tid = threadIdx.x, wid = tid >> 5, lane = tid & 31;
    int wm = wid >> 2;        // 0..1 : M half (32 rows)
    int wn = wid & 3;         // 0..3 : N quarter (64 cols)
    int m0 = blockIdx.x * TILE_M;
    int t0 = m0 & (T_ - 1);   // all 64 rows share batch b (T divisible by 64)
    int b  = m0 >> 13;

    // ---- early exit: t_mask is a prefix mask per batch. If the FIRST row of
    // this 64-row block is masked, every row is -> output is exactly zero.
    if (tmask[m0] == 0.f) {
        float4 z = make_float4(0.f, 0.f, 0.f, 0.f);
        float4* o4 = (float4*)(out + (size_t)m0 * DT);
        #pragma unroll
        for (int i = 0; i < 16; i++) o4[tid + 256 * i] = z;   // 64 rows x 64 float4
        return;
    }

    // prefetch B chunks 0,1 (stages 0,1)
    load_B_chunk(sb, 0, 0, tid);
    CP_COMMIT();
    load_B_chunk(sb, 1, 1, tid);
    CP_COMMIT();

    // ---- produce A tile (64 x 256) in smem as bf16 hi/lo, swizzled --------
    {
        float slen = g_slens[b];
        float wv0 = g_w[0], wv1 = g_w[1], wv2 = g_w[2];
        const float* mrow = s_mask + (size_t)b * S_;
        #pragma unroll 2
        for (int i = 0; i < 8; i++) {
            int row = wid * 8 + i;
            int t = t0 + row;
            float pos = (float)t * (1.0f / (float)(T_ - 1));
            float sp  = pos * (slen - 1.0f);
            int curr = (int)sp;
            int prev = max(curr - 1, 0);
            int nxt  = min(curr + 1, S_ - 1);
            float w0 = wv0 * mrow[prev];
            float w1 = wv1 * mrow[curr];
            float w2 = wv2 * mrow[nxt];
            const float4* ep = (const float4*)(emb + ((size_t)b * S_ + prev) * DIN);
            const float4* ec = (const float4*)(emb + ((size_t)b * S_ + curr) * DIN);
            const float4* en = (const float4*)(emb + ((size_t)b * S_ + nxt)  * DIN);
            float4 vp = ep[lane], vc = ec[lane], vn = en[lane];
            float v0 = w0 * vp.x + w1 * vc.x + w2 * vn.x;
            float v1 = w0 * vp.y + w1 * vc.y + w2 * vn.y;
            float v2 = w0 * vp.z + w1 * vc.z + w2 * vn.z;
            float v3 = w0 * vp.w + w1 * vc.w + w2 * vn.w;
            uint32_t h0; CVT2(h0, v0, v1);
            uint32_t h1; CVT2(h1, v2, v3);
            float l00 = v0 - __uint_as_float(h0 << 16);
            float l01 = v1 - __uint_as_float(h0 & 0xFFFF0000u);
            float l10 = v2 - __uint_as_float(h1 << 16);
            float l11 = v3 - __uint_as_float(h1 & 0xFFFF0000u);
            uint32_t q0; CVT2(q0, l00, l01);
            uint32_t q1; CVT2(q1, l10, l11);
            uint32_t rbase = row * 512;
            uint32_t rxor  = (row & 7) << 4;
            uint32_t o1 = rbase + ((8 * lane) ^ rxor);
            *(uint2*)(smem + OFF_A_HI + o1) = make_uint2(h0, h1);
            *(uint2*)(smem + OFF_A_LO + o1) = make_uint2(q0, q1);
            uint2 peh = *(const uint2*)(g_pehi + (size_t)t * 64 + 2 * lane);
            uint2 pel = *(const uint2*)(g_pelo + (size_t)t * 64 + 2 * lane);
            uint32_t o2 = rbase + ((256 + 8 * lane) ^ rxor);
            *(uint2*)(smem + OFF_A_HI + o2) = peh;
            *(uint2*)(smem + OFF_A_LO + o2) = pel;
        }
    }

    // ---- ldmatrix lane addressing ----
    int xr = (lane & 7) + ((lane >> 3) & 1) * 8;   // 0..15
    int xg = lane >> 4;                            // 0..1
    int a_row = wm * 32 + xr;
    uint32_t a_base = sb + OFF_A_HI + a_row * 512;
    uint32_t a_xor  = ((a_row & 7) << 4) ^ (xg * 16);
    uint32_t b_base = xr * 512;
    uint32_t b_xor  = (xr & 7) << 4;
    int b_col = wn * 128 + xg * 16;                // byte col base for this lane
    uint32_t co[4];
    #pragma unroll
    for (int p = 0; p < 4; p++) co[p] = ((uint32_t)(b_col + p * 32) ^ b_xor) + b_base;

    float acc[2][8][4];
    #pragma unroll
    for (int mt = 0; mt < 2; mt++)
        #pragma unroll
        for (int nt = 0; nt < 8; nt++)
            #pragma unroll
            for (int c = 0; c < 4; c++) acc[mt][nt][c] = 0.f;

    // ---- mainloop: 16 chunks of K=16, 3-stage pipeline --------------------
    int st = 0;
    for (int kc = 0; kc < 16; kc++) {
        if (kc == 15) { CP_WAIT0(); } else { CP_WAIT1(); }
        __syncthreads();
        if (kc < 14) {
            int nst = st + 2; if (nst >= 3) nst -= 3;
            load_B_chunk(sb, nst, kc + 2, tid);
            CP_COMMIT();
        }
        uint32_t bstage = sb + OFF_B0 + st * B_STAGE;
        uint32_t aoff = ((uint32_t)(kc * 32)) ^ a_xor;
        uint32_t Ahi[2][4], Alo[2][4];
        LDSM4(Ahi[0], a_base + aoff);
        LDSM4(Ahi[1], a_base + 16 * 512 + aoff);
        LDSM4(Alo[0], a_base + (OFF_A_LO - OFF_A_HI) + aoff);
        LDSM4(Alo[1], a_base + (OFF_A_LO - OFF_A_HI) + 16 * 512 + aoff);
        #pragma unroll
        for (int p = 0; p < 4; p++) {
            uint32_t Bhi[4], Blo[4];
            LDSM4T(Bhi, bstage + co[p]);
            LDSM4T(Blo, bstage + B_MAT + co[p]);
            // product-major: dependent MMAs on same acc are 4 apart
            mma_bf16(acc[0][2 * p],     Ahi[0], &Bhi[0]);
            mma_bf16(acc[0][2 * p + 1], Ahi[0], &Bhi[2]);
            mma_bf16(acc[1][2 * p],     Ahi[1], &Bhi[0]);
            mma_bf16(acc[1][2 * p + 1], Ahi[1], &Bhi[2]);
            mma_bf16(acc[0][2 * p],     Ahi[0], &Blo[0]);
            mma_bf16(acc[0][2 * p + 1], Ahi[0], &Blo[2]);
            mma_bf16(acc[1][2 * p],     Ahi[1], &Blo[0]);
            mma_bf16(acc[1][2 * p + 1], Ahi[1], &Blo[2]);
            mma_bf16(acc[0][2 * p],     Alo[0], &Bhi[0]);
            mma_bf16(acc[0][2 * p + 1], Alo[0], &Bhi[2]);
            mma_bf16(acc[1][2 * p],     Alo[1], &Bhi[0]);
            mma_bf16(acc[1][2 * p + 1], Alo[1], &Bhi[2]);
        }
        st = (st == 2) ? 0 : st + 1;
    }
    __syncthreads();   // frees B smem region for LN partial overlay

    // ---- epilogue: gelu + layernorm + mask (params straight from gmem) ----
    float* ps   = (float*)(smem + OFF_PS);
    float* ps2  = (float*)(smem + OFF_PS2);

    float2 bia[8], gg[8], be[8];
    #pragma unroll
    for (int nt = 0; nt < 8; nt++) {
        int c = wn * 64 + nt * 8 + 2 * (lane & 3);
        bia[nt] = *(const float2*)&bias[c];
        gg[nt]  = *(const float2*)&lng[c];
        be[nt]  = *(const float2*)&lnb[c];
    }

    #pragma unroll
    for (int mt = 0; mt < 2; mt++) {
        float sA = 0.f, s2A = 0.f, sB = 0.f, s2B = 0.f;
        #pragma unroll
        for (int nt = 0; nt < 8; nt++) {
            float v0 = gelu_exact(acc[mt][nt][0] + bia[nt].x);
            float v1 = gelu_exact(acc[mt][nt][1] + bia[nt].y);
            float v2 = gelu_exact(acc[mt][nt][2] + bia[nt].x);
            float v3 = gelu_exact(acc[mt][nt][3] + bia[nt].y);
            acc[mt][nt][0] = v0; acc[mt][nt][1] = v1;
            acc[mt][nt][2] = v2; acc[mt][nt][3] = v3;
            sA += v0 + v1; s2A += v0 * v0 + v1 * v1;
            sB += v2 + v3; s2B += v2 * v2 + v3 * v3;
        }
        #pragma unroll
        for (int o = 1; o <= 2; o <<= 1) {
            sA  += __shfl_xor_sync(0xFFFFFFFFu, sA,  o);
            s2A += __shfl_xor_sync(0xFFFFFFFFu, s2A, o);
            sB  += __shfl_xor_sync(0xFFFFFFFFu, sB,  o);
            s2B += __shfl_xor_sync(0xFFFFFFFFu, s2B, o);
        }
        if ((lane & 3) == 0) {
            int rA = wm * 32 + mt * 16 + (lane >> 2);
            ps[rA * 4 + wn]  = sA;  ps2[rA * 4 + wn]  = s2A;
            ps[(rA + 8) * 4 + wn] = sB; ps2[(rA + 8) * 4 + wn] = s2B;
        }
    }
    __syncthreads();

    #pragma unroll
    for (int mt = 0; mt < 2; mt++) {
        int rA = wm * 32 + mt * 16 + (lane >> 2);
        int rB = rA + 8;
        float tsA  = ps[rA * 4] + ps[rA * 4 + 1] + ps[rA * 4 + 2] + ps[rA * 4 + 3];
        float ts2A = ps2[rA * 4] + ps2[rA * 4 + 1] + ps2[rA * 4 + 2] + ps2[rA * 4 + 3];
        float tsB  = ps[rB * 4] + ps[rB * 4 + 1] + ps[rB * 4 + 2] + ps[rB * 4 + 3];
        float ts2B = ps2[rB * 4] + ps2[rB * 4 + 1] + ps2[rB * 4 + 2] + ps2[rB * 4 + 3];
        float muA = tsA * (1.f / 256.f);
        float muB = tsB * (1.f / 256.f);
        float invA = rsqrtf(ts2A * (1.f / 256.f) - muA * muA + 1e-5f);
        float invB = rsqrtf(ts2B * (1.f / 256.f) - muB * muB + 1e-5f);
        float mkA = tmask[m0 + rA];
        float mkB = tmask[m0 + rB];
        #pragma unroll
        for (int nt = 0; nt < 8; nt++) {
            int c = wn * 64 + nt * 8 + 2 * (lane & 3);
            float2 o1, o2;
            o1.x = ((acc[mt][nt][0] - muA) * invA * gg[nt].x + be[nt].x) * mkA;
            o1.y = ((acc[mt][nt][1] - muA) * invA * gg[nt].y + be[nt].y) * mkA;
            o2.x = ((acc[mt][nt][2] - muB) * invB * gg[nt].x + be[nt].x) * mkB;
            o2.y = ((acc[mt][nt][3] - muB) * invB * gg[nt].y + be[nt].y) * mkB;
            *(float2*)(out + (size_t)(m0 + rA) * DT + c) = o1;
            *(float2*)(out + (size_t)(m0 + rB) * DT + c) = o2;
        }
    }
}

// ---------------- launch ---------------------------------------------------
extern "C" void kernel_launch(void* const* d_in, const int* in_sizes, int n_in,
                              void* d_out, int out_size) {
    const float* student_emb = (const float*)d_in[0];
    const float* s_mask      = (const float*)d_in[1];
    const float* t_mask      = (const float*)d_in[2];
    int p = (in_sizes[3] == 64) ? 3 : 4;
    const float* pe_w1 = (const float*)d_in[p + 0];
    const float* pe_b1 = (const float*)d_in[p + 1];
    const float* pe_w2 = (const float*)d_in[p + 2];
    const float* pe_b2 = (const float*)d_in[p + 3];
    const float* pt_w  = (const float*)d_in[p + 4];
    const float* pt_b  = (const float*)d_in[p + 5];
    const float* ln_g  = (const float*)d_in[p + 6];
    const float* ln_b  = (const float*)d_in[p + 7];
    const float* nw    = (const float*)d_in[p + 8];
    float* out = (float*)d_out;

    cudaFuncSetAttribute(k_main, cudaFuncAttributeMaxDynamicSharedMemorySize, SMEM_TOTAL);

    k_prep<<<1, 1024>>>(s_mask, nw);
    k_posemb<<<T_, 128>>>(pe_w1, pe_b1, pe_w2, pe_b2);
    k_wsplit<<<DT * DT / 256, 256>>>(pt_w);
    k_main<<<NBLK, 256, SMEM_TOTAL>>>(student_emb, s_mask, t_mask,
                                      pt_b, ln_g, ln_b, out);
}